// round 6
// baseline (speedup 1.0000x reference)
#include <cuda_runtime.h>
#include <math.h>
#include <stdint.h>

#define NQ    12
#define DIM   4096
#define TT    8
#define BB    32
#define SHOTS 256
#define KMAX  80

typedef unsigned long long u64;

// Evolved states exp(-i t H)|init>, one complex vector per t, plus sync flags.
__device__ float2 g_states[TT][DIM];
__device__ int    g_flag[TT];   // 0 -> not ready, 1 -> ready (self-cleaning)
__device__ int    g_cnt[TT];    // consumer count for self-clean

__device__ __forceinline__ int ld_acquire(const int* p) {
    int v;
    asm volatile("ld.acquire.gpu.s32 %0, [%1];" : "=r"(v) : "l"(p) : "memory");
    return v;
}
__device__ __forceinline__ void st_release(int* p, int v) {
    asm volatile("st.release.gpu.s32 [%0], %1;" :: "l"(p), "r"(v) : "memory");
}
__device__ __forceinline__ uint32_t smem_u32(const void* p) {
    uint32_t a;
    asm("{ .reg .u64 t; cvta.to.shared.u64 t, %1; cvt.u32.u64 %0, t; }"
        : "=r"(a) : "l"(p));
    return a;
}

// ---- packed f32x2 helpers ----
__device__ __forceinline__ u64 pk2(float lo, float hi) {
    u64 r; asm("mov.b64 %0, {%1,%2};" : "=l"(r) : "f"(lo), "f"(hi)); return r;
}
__device__ __forceinline__ void upk2(u64 v, float& lo, float& hi) {
    asm("mov.b64 {%0,%1}, %2;" : "=f"(lo), "=f"(hi) : "l"(v));
}
__device__ __forceinline__ u64 fma2_(u64 a, u64 b, u64 c) {
    u64 d; asm("fma.rn.f32x2 %0, %1, %2, %3;" : "=l"(d) : "l"(a), "l"(b), "l"(c));
    return d;
}
__device__ __forceinline__ u64 mul2_(u64 a, u64 b) {
    u64 d; asm("mul.rn.f32x2 %0, %1, %2;" : "=l"(d) : "l"(a), "l"(b)); return d;
}

// ---------------------------------------------------------------------------
// One Chebyshev term. SO/DO: byte offsets of src/dst state buffers within the
// shared pool. EVEN: k parity (even -> real coefficient, odd -> imag).
// Ownership s=(e<<10)|(tid<<1)|c. Taps: bit0 = pair swap (regs),
// bits1..5 = lane bits (SHFL.BFLY), bits6..9 = smem (ld.shared.b64, packed),
// bits10..11 = e-dimension (regs).
// ---------------------------------------------------------------------------
template<int SO, int DO, bool EVEN>
__device__ __forceinline__ void cheb_term(
    u64 (&cur2)[4], float (&curs)[8], u64 (&prevn2)[4],
    u64 (&psr2)[4], u64 (&psi2)[4],
    const u64 (&diag2)[4], const u64 (&pxp)[12],
    const uint32_t (&tap_addr)[16], const uint32_t (&own_addr)[4],
    float coef)
{
    u64 a2[4];
#pragma unroll
    for (int e = 0; e < 4; e++) a2[e] = mul2_(diag2[e], cur2[e]);
    // bit 0: swap within pair
#pragma unroll
    for (int e = 0; e < 4; e++)
        a2[e] = fma2_(pxp[0], pk2(curs[2 * e + 1], curs[2 * e]), a2[e]);
    // bits 10, 11: e-dimension (registers)
#pragma unroll
    for (int e = 0; e < 4; e++) a2[e] = fma2_(pxp[10], cur2[e ^ 1], a2[e]);
#pragma unroll
    for (int e = 0; e < 4; e++) a2[e] = fma2_(pxp[11], cur2[e ^ 2], a2[e]);
    // bits 1..5: lane bits via shuffle
#pragma unroll
    for (int b = 1; b <= 5; b++) {
        const int m = 1 << (b - 1);
#pragma unroll
        for (int e = 0; e < 4; e++) {
            const float s0 = __shfl_xor_sync(0xffffffffu, curs[2 * e],     m);
            const float s1 = __shfl_xor_sync(0xffffffffu, curs[2 * e + 1], m);
            a2[e] = fma2_(pxp[b], pk2(s0, s1), a2[e]);
        }
    }
    // bits 6..9: shared memory (packed 8B loads, conflict-free)
#pragma unroll
    for (int b = 0; b < 4; b++) {
#pragma unroll
        for (int e = 0; e < 4; e++) {
            u64 v;
            asm("ld.shared.b64 %0, [%1+%2];"
                : "=l"(v) : "r"(tap_addr[b * 4 + e]), "n"(SO));
            a2[e] = fma2_(pxp[6 + b], v, a2[e]);
        }
    }
    const u64 TWO2 = pk2(2.f, 2.f);
    const u64 M12  = pk2(-1.f, -1.f);
    const u64 C2   = pk2(coef, coef);
#pragma unroll
    for (int e = 0; e < 4; e++) {
        const u64 nx = fma2_(TWO2, a2[e], prevn2[e]);   // 2*acc - prev
        prevn2[e] = mul2_(cur2[e], M12);
        cur2[e]   = nx;
        if (EVEN) psr2[e] = fma2_(C2, nx, psr2[e]);
        else      psi2[e] = fma2_(C2, nx, psi2[e]);
        asm volatile("st.shared.b64 [%0+%1], %2;"
                     :: "r"(own_addr[e]), "n"(DO), "l"(nx) : "memory");
    }
#pragma unroll
    for (int e = 0; e < 4; e++) upk2(cur2[e], curs[2 * e], curs[2 * e + 1]);
    __syncthreads();
}

// ---------------------------------------------------------------------------
// Fused persistent kernel. 256 CTAs x 512 threads.
//   bid < 8 : evolve t=bid (Chebyshev, state in smem), publish, then measure (t,0)
//   bid >= 8: wait on flag[t], then measure (t, b)
// ---------------------------------------------------------------------------
__global__ __launch_bounds__(512, 1)
void fused_kernel(const int* __restrict__ d_init,
                  const float* __restrict__ d_ts,
                  const int* __restrict__ d_pauli,
                  const int* __restrict__ d_idx,
                  const float* __restrict__ d_px,
                  const float* __restrict__ d_pzz,
                  float* __restrict__ d_out)
{
    // pool: evolve buf0 = [0,16KB), buf1 = [16KB,32KB), coeffs after.
    // measure reuses [0, DIM) = re, [DIM, 2*DIM) = im.
    __shared__ __align__(16) float pool[2 * DIM + 2 * (KMAX + 1)];
    __shared__ int s_misc[3 * NQ + 2];

    const int tid = threadIdx.x;
    const int bid = blockIdx.x;

    int t, b;
    if (bid < TT) { t = bid; b = 0; }
    else { const int j = bid - TT; t = j / 31; b = 1 + j % 31; }

    if (bid < TT) {
        // ================= EVOLVE (t = bid) =================
        float* s_cr = pool + 2 * DIM;
        float* s_ci = s_cr + (KMAX + 1);

        float px[NQ];
        float lambda = 0.f;
#pragma unroll
        for (int i = 0; i < NQ; i++) { px[i] = d_px[i]; lambda += fabsf(px[i]); }
        float pzz[NQ - 1];
#pragma unroll
        for (int i = 0; i < NQ - 1; i++) { pzz[i] = d_pzz[i]; lambda += fabsf(pzz[i]); }
        if (lambda < 1e-20f) lambda = 1e-20f;
        const float inv_l = 1.0f / lambda;
#pragma unroll
        for (int i = 0; i < NQ; i++) px[i] *= inv_l;

        u64 pxp[12];
#pragma unroll
        for (int i = 0; i < NQ; i++) pxp[i] = pk2(px[i], px[i]);

        // scaled diagonal for owned entries: s = (e<<10)|(tid<<1)|c
        float diag[8];
#pragma unroll
        for (int e = 0; e < 4; e++) {
#pragma unroll
            for (int c = 0; c < 2; c++) {
                const int s = (e << 10) | (tid << 1) | c;
                float d = 0.f;
#pragma unroll
                for (int i = 0; i < NQ - 1; i++) {
                    const int bi = (s >> i) & 1;
                    const int bj = (s >> (i + 1)) & 1;
                    d += (bi == bj) ? pzz[i] : -pzz[i];
                }
                diag[e * 2 + c] = d * inv_l;
            }
        }
        u64 diag2[4];
#pragma unroll
        for (int e = 0; e < 4; e++) diag2[e] = pk2(diag[2 * e], diag[2 * e + 1]);

        // thread 0: Bessel coefficients + adaptive trim
        if (tid == 0) {
            double x = (double)d_ts[t] * (double)lambda;
            if (x < 1e-5) x = 1e-5;
            int K = (int)ceil(x) + 16;
            if (K > KMAX) K = KMAX;
            if (K < 2)    K = 2;
            const int M = K + 14;
            double v[KMAX + 16];
            v[M] = 1e-30;
            const double inv_x = 1.0 / x;
            double up = 0.0;
            for (int k = M; k >= 1; k--) {
                const double nv = (2.0 * (double)k * inv_x) * v[k] - up;
                up = v[k];
                v[k - 1] = nv;
            }
            double S = v[0];
            for (int m = 2; m <= M; m += 2) S += 2.0 * v[m];
            const double invS = 1.0 / S;
            while (K > 2 && fabs(v[K] * invS) < 3e-5) K--;   // adaptive trim
            for (int k = 0; k <= K; k++) {
                const double Jk = v[k] * invS;
                const double c  = (k == 0) ? Jk : 2.0 * Jk;
                float cr = 0.f, ci = 0.f;
                switch (k & 3) {         // (-i)^k
                    case 0: cr = (float)c;  break;
                    case 1: ci = (float)-c; break;
                    case 2: cr = (float)-c; break;
                    case 3: ci = (float)c;  break;
                }
                s_cr[k] = cr;
                s_ci[k] = ci;
            }
            s_misc[0] = K;
        }
        __syncthreads();

        const int K    = s_misc[0];
        const int init = *d_init;

        // addresses: state pairs stored as u64 at index (e<<9)|tid
        const uint32_t base = smem_u32(pool);
        uint32_t own_addr[4];
        uint32_t tap_addr[16];
#pragma unroll
        for (int e = 0; e < 4; e++)
            own_addr[e] = base + (uint32_t)(((e << 9) | tid) << 3);
#pragma unroll
        for (int b2 = 0; b2 < 4; b2++) {
            const int pq = tid ^ (1 << (5 + b2));   // s-bit 6..9 <-> tid-bit 5..8
#pragma unroll
            for (int e = 0; e < 4; e++)
                tap_addr[b2 * 4 + e] = base + (uint32_t)(((e << 9) | pq) << 3);
        }

        // phi_0 = e_init ; phi_1 = H' e_init (analytic single column)
        float curs[8];
        u64 cur2[4], prevn2[4], psr2[4], psi2[4];
        const float cr0 = s_cr[0], ci1 = s_ci[1];
#pragma unroll
        for (int e = 0; e < 4; e++) {
            float p0v[2], p1v[2];
#pragma unroll
            for (int c = 0; c < 2; c++) {
                const int s = (e << 10) | (tid << 1) | c;
                p0v[c] = (s == init) ? 1.f : 0.f;
                float p1 = (s == init) ? diag[e * 2 + c] : 0.f;
                const int d = s ^ init;
#pragma unroll
                for (int i = 0; i < NQ; i++)
                    if (d == (1 << i)) p1 = px[i];
                p1v[c] = p1;
            }
            curs[2 * e]     = p1v[0];
            curs[2 * e + 1] = p1v[1];
            cur2[e]   = pk2(p1v[0], p1v[1]);
            prevn2[e] = pk2(-p0v[0], -p0v[1]);
            psr2[e]   = pk2(cr0 * p0v[0], cr0 * p0v[1]);
            psi2[e]   = pk2(ci1 * p1v[0], ci1 * p1v[1]);
            asm volatile("st.shared.b64 [%0], %1;"
                         :: "r"(own_addr[e]), "l"(cur2[e]) : "memory");
        }
        __syncthreads();

        for (int k = 2; k <= K; k += 2) {
            cheb_term<0, 16384, true>(cur2, curs, prevn2, psr2, psi2,
                                      diag2, pxp, tap_addr, own_addr, s_cr[k]);
            if (k + 1 <= K)
                cheb_term<16384, 0, false>(cur2, curs, prevn2, psr2, psi2,
                                           diag2, pxp, tap_addr, own_addr, s_ci[k + 1]);
        }

        // publish state + release flag
#pragma unroll
        for (int e = 0; e < 4; e++) {
            float r0, r1, i0, i1;
            upk2(psr2[e], r0, r1);
            upk2(psi2[e], i0, i1);
            const int s = (e << 10) | (tid << 1);
            g_states[t][s]     = make_float2(r0, i0);
            g_states[t][s | 1] = make_float2(r1, i1);
        }
        __syncthreads();
        if (tid == 0) {
            __threadfence();
            st_release(&g_flag[t], 1);
        }
        __syncthreads();   // pool reuse guard before measure phase
    } else {
        // ================= WAIT on evolve(t) =================
        if (tid == 0) {
            while (ld_acquire(&g_flag[t]) == 0) __nanosleep(128);
            const int n = atomicAdd(&g_cnt[t], 1);
            if (n == 30) {               // last of 31 waiters: self-clean
                g_cnt[t]  = 0;
                g_flag[t] = 0;
            }
        }
        __syncthreads();
    }

    // ================= MEASURE (t, b) =================
    {
        float* re = pool;
        float* im = pool + DIM;
        int* p_raw = s_misc;
        int* nzm   = s_misc + NQ;
        int* nzp   = s_misc + 2 * NQ;
        int* s_nnz = s_misc + 3 * NQ;

        if (tid < NQ) p_raw[tid] = d_pauli[b * NQ + tid];

#pragma unroll
        for (int r = 0; r < DIM / 512; r++) {
            const int s = tid + (r << 9);
            const float2 v = __ldcg(&g_states[t][s]);
            re[s] = v.x;
            im[s] = v.y;
        }
        __syncthreads();

        if (tid == 0) {
            int c = 0;
            for (int m = NQ - 1; m >= 0; m--) {
                const int p = p_raw[NQ - 1 - m];
                if (p != 2) { nzm[c] = m; nzp[c] = p; c++; }
            }
            *s_nnz = c;
        }
        __syncthreads();

        const int nnz = *s_nnz;
        int i = 0;
        for (; i + 1 < nnz; i += 2) {
            const int mh = nzm[i], ml = nzm[i + 1];
            const int ph_ = nzp[i], pl = nzp[i + 1];
            const int lml = (1 << ml) - 1;
            const int lmh = (1 << mh) - 1;
#pragma unroll
            for (int r = 0; r < (DIM / 4) / 512; r++) {
                const int g  = tid + (r << 9);
                const int x  = ((g & ~lml) << 1) | (g & lml);
                const int s00 = ((x & ~lmh) << 1) | (x & lmh);
                const int s01 = s00 | (1 << ml);
                const int s10 = s00 | (1 << mh);
                const int s11 = s10 | (1 << ml);
                const float r00 = re[s00], i00 = im[s00];
                const float r01 = re[s01], i01 = im[s01];
                const float r10 = re[s10], i10 = im[s10];
                const float r11 = re[s11], i11 = im[s11];
                float a0r, a0i, a1r, a1i, b0r, b0i, b1r, b1i;
                if (pl == 0) {
                    a0r = r00 + r01; a0i = i00 + i01; a1r = r00 - r01; a1i = i00 - i01;
                    b0r = r10 + r11; b0i = i10 + i11; b1r = r10 - r11; b1i = i10 - i11;
                } else {
                    a0r = r00 + i01; a0i = i00 - r01; a1r = r00 - i01; a1i = i00 + r01;
                    b0r = r10 + i11; b0i = i10 - r11; b1r = r10 - i11; b1i = i10 + r11;
                }
                float o00r, o00i, o01r, o01i, o10r, o10i, o11r, o11i;
                if (ph_ == 0) {
                    o00r = a0r + b0r; o00i = a0i + b0i; o10r = a0r - b0r; o10i = a0i - b0i;
                    o01r = a1r + b1r; o01i = a1i + b1i; o11r = a1r - b1r; o11i = a1i - b1i;
                } else {
                    o00r = a0r + b0i; o00i = a0i - b0r; o10r = a0r - b0i; o10i = a0i + b0r;
                    o01r = a1r + b1i; o01i = a1i - b1r; o11r = a1r - b1i; o11i = a1i + b1r;
                }
                re[s00] = o00r * 0.5f; im[s00] = o00i * 0.5f;
                re[s01] = o01r * 0.5f; im[s01] = o01i * 0.5f;
                re[s10] = o10r * 0.5f; im[s10] = o10i * 0.5f;
                re[s11] = o11r * 0.5f; im[s11] = o11i * 0.5f;
            }
            __syncthreads();
        }
        if (i < nnz) {
            const int m = nzm[i], p = nzp[i];
            const int lm = (1 << m) - 1;
            const float s2 = 0.70710678118654752f;
#pragma unroll
            for (int r = 0; r < (DIM / 2) / 512; r++) {
                const int q  = tid + (r << 9);
                const int s0 = ((q & ~lm) << 1) | (q & lm);
                const int s1 = s0 | (1 << m);
                const float r0 = re[s0], i0 = im[s0];
                const float r1 = re[s1], i1 = im[s1];
                float nr0, ni0, nr1, ni1;
                if (p == 0) { nr0 = r0 + r1; ni0 = i0 + i1; nr1 = r0 - r1; ni1 = i0 - i1; }
                else        { nr0 = r0 + i1; ni0 = i0 - r1; nr1 = r0 - i1; ni1 = i0 + r1; }
                re[s0] = nr0 * s2; im[s0] = ni0 * s2;
                re[s1] = nr1 * s2; im[s1] = ni1 * s2;
            }
            __syncthreads();
        }

        if (tid < SHOTS) {
            const int base2 = (t * BB + b) * SHOTS;
            const int idx   = d_idx[base2 + tid];
            const float pr  = re[idx];
            const float pi  = im[idx];
            d_out[base2 + tid] = pr * pr + pi * pi;
        }
    }
}

// ---------------------------------------------------------------------------
extern "C" void kernel_launch(void* const* d_in, const int* in_sizes, int n_in,
                              void* d_out, int out_size)
{
    const int*   d_init  = (const int*)  d_in[0];
    const float* d_ts    = (const float*)d_in[1];
    const int*   d_pauli = (const int*)  d_in[2];
    const int*   d_idx   = (const int*)  d_in[3];
    const float* d_px    = (const float*)d_in[4];
    const float* d_pzz   = (const float*)d_in[5];

    fused_kernel<<<TT * BB, 512>>>(d_init, d_ts, d_pauli, d_idx,
                                   d_px, d_pzz, (float*)d_out);
}

// round 7
// speedup vs baseline: 1.0789x; 1.0789x over previous
#include <cuda_runtime.h>
#include <math.h>
#include <stdint.h>

#define NQ    12
#define DIM   4096
#define TT    8
#define BB    32
#define SHOTS 256
#define KMAX  80

typedef unsigned long long u64;

// Evolved states exp(-i t H)|init>, one complex vector per t, plus sync flags.
__device__ float2 g_states[TT][DIM];
__device__ int    g_flag[TT];   // 0 -> not ready, 1 -> ready (self-cleaning)
__device__ int    g_cnt[TT];    // consumer count for self-clean

__device__ __forceinline__ int ld_acquire(const int* p) {
    int v;
    asm volatile("ld.acquire.gpu.s32 %0, [%1];" : "=r"(v) : "l"(p) : "memory");
    return v;
}
__device__ __forceinline__ void st_release(int* p, int v) {
    asm volatile("st.release.gpu.s32 [%0], %1;" :: "l"(p), "r"(v) : "memory");
}

// ---- packed f32x2 helpers ----
__device__ __forceinline__ u64 pk2(float lo, float hi) {
    u64 r; asm("mov.b64 %0, {%1,%2};" : "=l"(r) : "f"(lo), "f"(hi)); return r;
}
__device__ __forceinline__ void upk2(u64 v, float& lo, float& hi) {
    asm("mov.b64 {%0,%1}, %2;" : "=f"(lo), "=f"(hi) : "l"(v));
}
__device__ __forceinline__ u64 fma2_(u64 a, u64 b, u64 c) {
    u64 d; asm("fma.rn.f32x2 %0, %1, %2, %3;" : "=l"(d) : "l"(a), "l"(b), "l"(c));
    return d;
}
__device__ __forceinline__ u64 mul2_(u64 a, u64 b) {
    u64 d; asm("mul.rn.f32x2 %0, %1, %2;" : "=l"(d) : "l"(a), "l"(b)); return d;
}

// ---------------------------------------------------------------------------
// One Chebyshev term, pure-smem taps, packed math.
// Ownership s=(e<<10)|(tid<<1)|c. Taps: bit0 = pair swap (regs),
// bits1..9 = smem (ld.shared.b64 via 9 partner pointers, e as imm offset),
// bits10..11 = e-dimension (regs).
// SRC/DST: u64 state buffers (2048 pairs each), EVEN: k parity.
// ---------------------------------------------------------------------------
template<bool EVEN>
__device__ __forceinline__ void cheb_term(
    u64 (&cur2)[4], float (&curs)[8], u64 (&prevn2)[4],
    u64 (&psr2)[4], u64 (&psi2)[4],
    const u64 (&diag2)[4], const u64 (&pxp)[12],
    const u64* __restrict__ SRC, u64* __restrict__ DST,
    const int (&pq)[9], int tid, float coef)
{
    u64 a2[4];
#pragma unroll
    for (int e = 0; e < 4; e++) a2[e] = mul2_(diag2[e], cur2[e]);
    // bit 0: swap within pair (registers)
#pragma unroll
    for (int e = 0; e < 4; e++)
        a2[e] = fma2_(pxp[0], pk2(curs[2 * e + 1], curs[2 * e]), a2[e]);
    // bits 10, 11: e-dimension (registers)
#pragma unroll
    for (int e = 0; e < 4; e++) a2[e] = fma2_(pxp[10], cur2[e ^ 1], a2[e]);
#pragma unroll
    for (int e = 0; e < 4; e++) a2[e] = fma2_(pxp[11], cur2[e ^ 2], a2[e]);
    // bits 1..9: shared memory taps (conflict-free b64, imm e-offsets)
#pragma unroll
    for (int bi = 0; bi < 9; bi++) {
        const u64* p = SRC + pq[bi];
#pragma unroll
        for (int e = 0; e < 4; e++)
            a2[e] = fma2_(pxp[1 + bi], p[e << 9], a2[e]);
    }
    const u64 TWO2 = pk2(2.f, 2.f);
    const u64 M12  = pk2(-1.f, -1.f);
    const u64 C2   = pk2(coef, coef);
#pragma unroll
    for (int e = 0; e < 4; e++) {
        const u64 nx = fma2_(TWO2, a2[e], prevn2[e]);   // 2*acc - prev
        prevn2[e] = mul2_(cur2[e], M12);
        cur2[e]   = nx;
        if (EVEN) psr2[e] = fma2_(C2, nx, psr2[e]);
        else      psi2[e] = fma2_(C2, nx, psi2[e]);
        DST[(e << 9) | tid] = nx;
    }
#pragma unroll
    for (int e = 0; e < 4; e++) upk2(cur2[e], curs[2 * e], curs[2 * e + 1]);
    __syncthreads();
}

// ---------------------------------------------------------------------------
// Fused persistent kernel. 256 CTAs x 512 threads.
//   bid < 8 : evolve t=bid (Chebyshev, state in smem), publish, then measure (t,0)
//   bid >= 8: wait on flag[t], then measure (t, b)
// ---------------------------------------------------------------------------
__global__ __launch_bounds__(512, 1)
void fused_kernel(const int* __restrict__ d_init,
                  const float* __restrict__ d_ts,
                  const int* __restrict__ d_pauli,
                  const int* __restrict__ d_idx,
                  const float* __restrict__ d_px,
                  const float* __restrict__ d_pzz,
                  float* __restrict__ d_out)
{
    // pool: evolve buf0 = [0,16KB), buf1 = [16KB,32KB), coeffs after.
    // measure reuses [0, DIM) = re, [DIM, 2*DIM) = im.
    __shared__ __align__(16) float pool[2 * DIM + 2 * (KMAX + 1)];
    __shared__ int s_misc[3 * NQ + 2];

    const int tid = threadIdx.x;
    const int bid = blockIdx.x;

    int t, b;
    if (bid < TT) { t = bid; b = 0; }
    else { const int j = bid - TT; t = j / 31; b = 1 + j % 31; }

    if (bid < TT) {
        // ================= EVOLVE (t = bid) =================
        u64* buf0 = reinterpret_cast<u64*>(pool);
        u64* buf1 = buf0 + DIM / 2;
        float* s_cr = pool + 2 * DIM;
        float* s_ci = s_cr + (KMAX + 1);

        float px[NQ];
        float lambda = 0.f;
#pragma unroll
        for (int i = 0; i < NQ; i++) { px[i] = d_px[i]; lambda += fabsf(px[i]); }
        float pzz[NQ - 1];
#pragma unroll
        for (int i = 0; i < NQ - 1; i++) { pzz[i] = d_pzz[i]; lambda += fabsf(pzz[i]); }
        if (lambda < 1e-20f) lambda = 1e-20f;
        const float inv_l = 1.0f / lambda;
#pragma unroll
        for (int i = 0; i < NQ; i++) px[i] *= inv_l;

        u64 pxp[12];
#pragma unroll
        for (int i = 0; i < NQ; i++) pxp[i] = pk2(px[i], px[i]);

        // scaled diagonal for owned entries: s = (e<<10)|(tid<<1)|c
        float diag[8];
#pragma unroll
        for (int e = 0; e < 4; e++) {
#pragma unroll
            for (int c = 0; c < 2; c++) {
                const int s = (e << 10) | (tid << 1) | c;
                float d = 0.f;
#pragma unroll
                for (int i = 0; i < NQ - 1; i++) {
                    const int bi = (s >> i) & 1;
                    const int bj = (s >> (i + 1)) & 1;
                    d += (bi == bj) ? pzz[i] : -pzz[i];
                }
                diag[e * 2 + c] = d * inv_l;
            }
        }
        u64 diag2[4];
#pragma unroll
        for (int e = 0; e < 4; e++) diag2[e] = pk2(diag[2 * e], diag[2 * e + 1]);

        // thread 0: Bessel coefficients + adaptive trim
        if (tid == 0) {
            double x = (double)d_ts[t] * (double)lambda;
            if (x < 1e-5) x = 1e-5;
            int K = (int)ceil(x) + 16;
            if (K > KMAX) K = KMAX;
            if (K < 2)    K = 2;
            const int M = K + 14;
            double v[KMAX + 16];
            v[M] = 1e-30;
            const double inv_x = 1.0 / x;
            double up = 0.0;
            for (int k = M; k >= 1; k--) {
                const double nv = (2.0 * (double)k * inv_x) * v[k] - up;
                up = v[k];
                v[k - 1] = nv;
            }
            double S = v[0];
            for (int m = 2; m <= M; m += 2) S += 2.0 * v[m];
            const double invS = 1.0 / S;
            while (K > 2 && fabs(v[K] * invS) < 2e-4) K--;   // adaptive trim
            for (int k = 0; k <= K; k++) {
                const double Jk = v[k] * invS;
                const double c  = (k == 0) ? Jk : 2.0 * Jk;
                float cr = 0.f, ci = 0.f;
                switch (k & 3) {         // (-i)^k
                    case 0: cr = (float)c;  break;
                    case 1: ci = (float)-c; break;
                    case 2: cr = (float)-c; break;
                    case 3: ci = (float)c;  break;
                }
                s_cr[k] = cr;
                s_ci[k] = ci;
            }
            s_misc[0] = K;
        }
        __syncthreads();

        const int K    = s_misc[0];
        const int init = *d_init;

        // loop-invariant partner pair-indices for smem-tap bits 1..9
        int pq[9];
#pragma unroll
        for (int b2 = 1; b2 <= 9; b2++)
            pq[b2 - 1] = tid ^ (1 << (b2 - 1));

        // phi_0 = e_init ; phi_1 = H' e_init (analytic single column)
        float curs[8];
        u64 cur2[4], prevn2[4], psr2[4], psi2[4];
        const float cr0 = s_cr[0], ci1 = s_ci[1];
#pragma unroll
        for (int e = 0; e < 4; e++) {
            float p0v[2], p1v[2];
#pragma unroll
            for (int c = 0; c < 2; c++) {
                const int s = (e << 10) | (tid << 1) | c;
                p0v[c] = (s == init) ? 1.f : 0.f;
                float p1 = (s == init) ? diag[e * 2 + c] : 0.f;
                const int d = s ^ init;
#pragma unroll
                for (int i = 0; i < NQ; i++)
                    if (d == (1 << i)) p1 = px[i];
                p1v[c] = p1;
            }
            curs[2 * e]     = p1v[0];
            curs[2 * e + 1] = p1v[1];
            cur2[e]   = pk2(p1v[0], p1v[1]);
            prevn2[e] = pk2(-p0v[0], -p0v[1]);
            psr2[e]   = pk2(cr0 * p0v[0], cr0 * p0v[1]);
            psi2[e]   = pk2(ci1 * p1v[0], ci1 * p1v[1]);
            buf0[(e << 9) | tid] = cur2[e];
        }
        __syncthreads();

        for (int k = 2; k <= K; k += 2) {
            cheb_term<true>(cur2, curs, prevn2, psr2, psi2,
                            diag2, pxp, buf0, buf1, pq, tid, s_cr[k]);
            if (k + 1 <= K)
                cheb_term<false>(cur2, curs, prevn2, psr2, psi2,
                                 diag2, pxp, buf1, buf0, pq, tid, s_ci[k + 1]);
        }

        // publish state + release flag
#pragma unroll
        for (int e = 0; e < 4; e++) {
            float r0, r1, i0, i1;
            upk2(psr2[e], r0, r1);
            upk2(psi2[e], i0, i1);
            const int s = (e << 10) | (tid << 1);
            g_states[t][s]     = make_float2(r0, i0);
            g_states[t][s | 1] = make_float2(r1, i1);
        }
        __syncthreads();
        if (tid == 0) {
            __threadfence();
            st_release(&g_flag[t], 1);
        }
        __syncthreads();   // pool reuse guard before measure phase
    } else {
        // ================= WAIT on evolve(t) =================
        if (tid == 0) {
            while (ld_acquire(&g_flag[t]) == 0) __nanosleep(128);
            const int n = atomicAdd(&g_cnt[t], 1);
            if (n == 30) {               // last of 31 waiters: self-clean
                g_cnt[t]  = 0;
                g_flag[t] = 0;
            }
        }
        __syncthreads();
    }

    // ================= MEASURE (t, b) =================
    {
        float* re = pool;
        float* im = pool + DIM;
        int* p_raw = s_misc;
        int* nzm   = s_misc + NQ;
        int* nzp   = s_misc + 2 * NQ;
        int* s_nnz = s_misc + 3 * NQ;

        if (tid < NQ) p_raw[tid] = d_pauli[b * NQ + tid];

#pragma unroll
        for (int r = 0; r < DIM / 512; r++) {
            const int s = tid + (r << 9);
            const float2 v = __ldcg(&g_states[t][s]);
            re[s] = v.x;
            im[s] = v.y;
        }
        __syncthreads();

        if (tid == 0) {
            int c = 0;
            for (int m = NQ - 1; m >= 0; m--) {
                const int p = p_raw[NQ - 1 - m];
                if (p != 2) { nzm[c] = m; nzp[c] = p; c++; }
            }
            *s_nnz = c;
        }
        __syncthreads();

        const int nnz = *s_nnz;
        int i = 0;
        for (; i + 1 < nnz; i += 2) {
            const int mh = nzm[i], ml = nzm[i + 1];
            const int ph_ = nzp[i], pl = nzp[i + 1];
            const int lml = (1 << ml) - 1;
            const int lmh = (1 << mh) - 1;
#pragma unroll
            for (int r = 0; r < (DIM / 4) / 512; r++) {
                const int g  = tid + (r << 9);
                const int x  = ((g & ~lml) << 1) | (g & lml);
                const int s00 = ((x & ~lmh) << 1) | (x & lmh);
                const int s01 = s00 | (1 << ml);
                const int s10 = s00 | (1 << mh);
                const int s11 = s10 | (1 << ml);
                const float r00 = re[s00], i00 = im[s00];
                const float r01 = re[s01], i01 = im[s01];
                const float r10 = re[s10], i10 = im[s10];
                const float r11 = re[s11], i11 = im[s11];
                float a0r, a0i, a1r, a1i, b0r, b0i, b1r, b1i;
                if (pl == 0) {
                    a0r = r00 + r01; a0i = i00 + i01; a1r = r00 - r01; a1i = i00 - i01;
                    b0r = r10 + r11; b0i = i10 + i11; b1r = r10 - r11; b1i = i10 - i11;
                } else {
                    a0r = r00 + i01; a0i = i00 - r01; a1r = r00 - i01; a1i = i00 + r01;
                    b0r = r10 + i11; b0i = i10 - r11; b1r = r10 - i11; b1i = i10 + r11;
                }
                float o00r, o00i, o01r, o01i, o10r, o10i, o11r, o11i;
                if (ph_ == 0) {
                    o00r = a0r + b0r; o00i = a0i + b0i; o10r = a0r - b0r; o10i = a0i - b0i;
                    o01r = a1r + b1r; o01i = a1i + b1i; o11r = a1r - b1r; o11i = a1i - b1i;
                } else {
                    o00r = a0r + b0i; o00i = a0i - b0r; o10r = a0r - b0i; o10i = a0i + b0r;
                    o01r = a1r + b1i; o01i = a1i - b1r; o11r = a1r - b1i; o11i = a1i + b1r;
                }
                re[s00] = o00r * 0.5f; im[s00] = o00i * 0.5f;
                re[s01] = o01r * 0.5f; im[s01] = o01i * 0.5f;
                re[s10] = o10r * 0.5f; im[s10] = o10i * 0.5f;
                re[s11] = o11r * 0.5f; im[s11] = o11i * 0.5f;
            }
            __syncthreads();
        }
        if (i < nnz) {
            const int m = nzm[i], p = nzp[i];
            const int lm = (1 << m) - 1;
            const float s2 = 0.70710678118654752f;
#pragma unroll
            for (int r = 0; r < (DIM / 2) / 512; r++) {
                const int q  = tid + (r << 9);
                const int s0 = ((q & ~lm) << 1) | (q & lm);
                const int s1 = s0 | (1 << m);
                const float r0 = re[s0], i0 = im[s0];
                const float r1 = re[s1], i1 = im[s1];
                float nr0, ni0, nr1, ni1;
                if (p == 0) { nr0 = r0 + r1; ni0 = i0 + i1; nr1 = r0 - r1; ni1 = i0 - i1; }
                else        { nr0 = r0 + i1; ni0 = i0 - r1; nr1 = r0 - i1; ni1 = i0 + r1; }
                re[s0] = nr0 * s2; im[s0] = ni0 * s2;
                re[s1] = nr1 * s2; im[s1] = ni1 * s2;
            }
            __syncthreads();
        }

        if (tid < SHOTS) {
            const int base2 = (t * BB + b) * SHOTS;
            const int idx   = d_idx[base2 + tid];
            const float pr  = re[idx];
            const float pi  = im[idx];
            d_out[base2 + tid] = pr * pr + pi * pi;
        }
    }
}

// ---------------------------------------------------------------------------
extern "C" void kernel_launch(void* const* d_in, const int* in_sizes, int n_in,
                              void* d_out, int out_size)
{
    const int*   d_init  = (const int*)  d_in[0];
    const float* d_ts    = (const float*)d_in[1];
    const int*   d_pauli = (const int*)  d_in[2];
    const int*   d_idx   = (const int*)  d_in[3];
    const float* d_px    = (const float*)d_in[4];
    const float* d_pzz   = (const float*)d_in[5];

    fused_kernel<<<TT * BB, 512>>>(d_init, d_ts, d_pauli, d_idx,
                                   d_px, d_pzz, (float*)d_out);
}

// round 8
// speedup vs baseline: 1.0986x; 1.0183x over previous
#include <cuda_runtime.h>
#include <math.h>
#include <stdint.h>

#define NQ    12
#define DIM   4096
#define TT    8
#define BB    32
#define SHOTS 256
#define KMAX  80

typedef unsigned long long u64;

// Evolved states exp(-i t H)|init>, one complex vector per t, plus sync flags.
__device__ float2 g_states[TT][DIM];
__device__ int    g_flag[TT];   // 0 -> not ready, 1 -> ready (self-cleaning)
__device__ int    g_cnt[TT];    // consumer count for self-clean

__device__ __forceinline__ int ld_acquire(const int* p) {
    int v;
    asm volatile("ld.acquire.gpu.s32 %0, [%1];" : "=r"(v) : "l"(p) : "memory");
    return v;
}
__device__ __forceinline__ void st_release(int* p, int v) {
    asm volatile("st.release.gpu.s32 [%0], %1;" :: "l"(p), "r"(v) : "memory");
}

// ---- packed f32x2 helpers ----
__device__ __forceinline__ u64 pk2(float lo, float hi) {
    u64 r; asm("mov.b64 %0, {%1,%2};" : "=l"(r) : "f"(lo), "f"(hi)); return r;
}
__device__ __forceinline__ void upk2(u64 v, float& lo, float& hi) {
    asm("mov.b64 {%0,%1}, %2;" : "=f"(lo), "=f"(hi) : "l"(v));
}
__device__ __forceinline__ u64 fma2_(u64 a, u64 b, u64 c) {
    u64 d; asm("fma.rn.f32x2 %0, %1, %2, %3;" : "=l"(d) : "l"(a), "l"(b), "l"(c));
    return d;
}
__device__ __forceinline__ u64 mul2_(u64 a, u64 b) {
    u64 d; asm("mul.rn.f32x2 %0, %1, %2;" : "=l"(d) : "l"(a), "l"(b)); return d;
}

// ---------------------------------------------------------------------------
// One Chebyshev term with barrier-overlap split.
// Ownership s=(e<<10)|(tid<<1)|c; pair index (e<<9)|tid.
// Taps: bit0 = pair swap (regs); bits1..5 = INTRA-warp smem (lane bits,
// warp-synchronous — issued BEFORE the CTA barrier); bits6..9 = CROSS-warp
// smem (after barrier); bits10..11 = e-dimension (regs).
// The single __syncthreads sits mid-term, overlapped by ~40 independent
// instructions on both sides. No trailing barrier (double buffer + the next
// term's mid-barrier make it safe; max warp skew = 1 term).
// ---------------------------------------------------------------------------
template<bool EVEN>
__device__ __forceinline__ void cheb_term(
    u64 (&cur2)[4], float (&curs)[8], u64 (&prevn2)[4],
    u64 (&psr2)[4], u64 (&psi2)[4],
    const u64 (&diag2)[4], const u64 (&pxp)[12],
    const u64* __restrict__ SRC, u64* __restrict__ DST,
    const int (&pqi)[5], const int (&pqx)[4], int tid, float coef)
{
    u64 a2[4];
    // register taps: diag, bit0 swap, bits 10-11
#pragma unroll
    for (int e = 0; e < 4; e++) a2[e] = mul2_(diag2[e], cur2[e]);
#pragma unroll
    for (int e = 0; e < 4; e++)
        a2[e] = fma2_(pxp[0], pk2(curs[2 * e + 1], curs[2 * e]), a2[e]);
#pragma unroll
    for (int e = 0; e < 4; e++) a2[e] = fma2_(pxp[10], cur2[e ^ 1], a2[e]);
#pragma unroll
    for (int e = 0; e < 4; e++) a2[e] = fma2_(pxp[11], cur2[e ^ 2], a2[e]);

    // intra-warp taps, bits 1..5 (own warp's stores; warp-synchronous)
    __syncwarp();
#pragma unroll
    for (int bi = 0; bi < 5; bi++) {
        const u64* p = SRC + pqi[bi];
#pragma unroll
        for (int e = 0; e < 4; e++)
            a2[e] = fma2_(pxp[1 + bi], p[e << 9], a2[e]);
    }

    __syncthreads();   // cross-warp visibility of SRC; overlapped by loads above

    // cross-warp taps, bits 6..9
#pragma unroll
    for (int bi = 0; bi < 4; bi++) {
        const u64* p = SRC + pqx[bi];
#pragma unroll
        for (int e = 0; e < 4; e++)
            a2[e] = fma2_(pxp[6 + bi], p[e << 9], a2[e]);
    }

    const u64 TWO2 = pk2(2.f, 2.f);
    const u64 M12  = pk2(-1.f, -1.f);
    const u64 C2   = pk2(coef, coef);
#pragma unroll
    for (int e = 0; e < 4; e++) {
        const u64 nx = fma2_(TWO2, a2[e], prevn2[e]);   // 2*acc - prev
        DST[(e << 9) | tid] = nx;                        // publish early
        prevn2[e] = mul2_(cur2[e], M12);
        cur2[e]   = nx;
        if (EVEN) psr2[e] = fma2_(C2, nx, psr2[e]);
        else      psi2[e] = fma2_(C2, nx, psi2[e]);
    }
#pragma unroll
    for (int e = 0; e < 4; e++) upk2(cur2[e], curs[2 * e], curs[2 * e + 1]);
}

// ---------------------------------------------------------------------------
// Fused persistent kernel. 256 CTAs x 512 threads.
//   bid < 8 : evolve t=bid (Chebyshev, state in smem), publish, then measure (t,0)
//   bid >= 8: wait on flag[t], then measure (t, b)
// ---------------------------------------------------------------------------
__global__ __launch_bounds__(512, 1)
void fused_kernel(const int* __restrict__ d_init,
                  const float* __restrict__ d_ts,
                  const int* __restrict__ d_pauli,
                  const int* __restrict__ d_idx,
                  const float* __restrict__ d_px,
                  const float* __restrict__ d_pzz,
                  float* __restrict__ d_out)
{
    // pool: evolve buf0 = [0,16KB), buf1 = [16KB,32KB), coeffs after.
    // measure reuses [0, DIM) = re, [DIM, 2*DIM) = im.
    __shared__ __align__(16) float pool[2 * DIM + 2 * (KMAX + 1)];
    __shared__ int s_misc[3 * NQ + 2];

    const int tid = threadIdx.x;
    const int bid = blockIdx.x;

    int t, b;
    if (bid < TT) { t = bid; b = 0; }
    else { const int j = bid - TT; t = j / 31; b = 1 + j % 31; }

    if (bid < TT) {
        // ================= EVOLVE (t = bid) =================
        u64* buf0 = reinterpret_cast<u64*>(pool);
        u64* buf1 = buf0 + DIM / 2;
        float* s_cr = pool + 2 * DIM;
        float* s_ci = s_cr + (KMAX + 1);

        float px[NQ];
        float lambda = 0.f;
#pragma unroll
        for (int i = 0; i < NQ; i++) { px[i] = d_px[i]; lambda += fabsf(px[i]); }
        float pzz[NQ - 1];
#pragma unroll
        for (int i = 0; i < NQ - 1; i++) { pzz[i] = d_pzz[i]; lambda += fabsf(pzz[i]); }
        if (lambda < 1e-20f) lambda = 1e-20f;
        const float inv_l = 1.0f / lambda;
#pragma unroll
        for (int i = 0; i < NQ; i++) px[i] *= inv_l;

        u64 pxp[12];
#pragma unroll
        for (int i = 0; i < NQ; i++) pxp[i] = pk2(px[i], px[i]);

        // scaled diagonal for owned entries: s = (e<<10)|(tid<<1)|c
        float diag[8];
#pragma unroll
        for (int e = 0; e < 4; e++) {
#pragma unroll
            for (int c = 0; c < 2; c++) {
                const int s = (e << 10) | (tid << 1) | c;
                float d = 0.f;
#pragma unroll
                for (int i = 0; i < NQ - 1; i++) {
                    const int bi = (s >> i) & 1;
                    const int bj = (s >> (i + 1)) & 1;
                    d += (bi == bj) ? pzz[i] : -pzz[i];
                }
                diag[e * 2 + c] = d * inv_l;
            }
        }
        u64 diag2[4];
#pragma unroll
        for (int e = 0; e < 4; e++) diag2[e] = pk2(diag[2 * e], diag[2 * e + 1]);

        // thread 0: Bessel coefficients + adaptive trim
        if (tid == 0) {
            double x = (double)d_ts[t] * (double)lambda;
            if (x < 1e-5) x = 1e-5;
            int K = (int)ceil(x) + 16;
            if (K > KMAX) K = KMAX;
            if (K < 2)    K = 2;
            const int M = K + 14;
            double v[KMAX + 16];
            v[M] = 1e-30;
            const double inv_x = 1.0 / x;
            double up = 0.0;
            for (int k = M; k >= 1; k--) {
                const double nv = (2.0 * (double)k * inv_x) * v[k] - up;
                up = v[k];
                v[k - 1] = nv;
            }
            double S = v[0];
            for (int m = 2; m <= M; m += 2) S += 2.0 * v[m];
            const double invS = 1.0 / S;
            while (K > 2 && fabs(v[K] * invS) < 2e-4) K--;   // adaptive trim
            for (int k = 0; k <= K; k++) {
                const double Jk = v[k] * invS;
                const double c  = (k == 0) ? Jk : 2.0 * Jk;
                float cr = 0.f, ci = 0.f;
                switch (k & 3) {         // (-i)^k
                    case 0: cr = (float)c;  break;
                    case 1: ci = (float)-c; break;
                    case 2: cr = (float)-c; break;
                    case 3: ci = (float)c;  break;
                }
                s_cr[k] = cr;
                s_ci[k] = ci;
            }
            s_misc[0] = K;
        }
        __syncthreads();

        const int K    = s_misc[0];
        const int init = *d_init;

        // loop-invariant partner pair-indices: intra-warp (bits1-5), cross (6-9)
        int pqi[5], pqx[4];
#pragma unroll
        for (int b2 = 0; b2 < 5; b2++) pqi[b2] = tid ^ (1 << b2);
#pragma unroll
        for (int b2 = 0; b2 < 4; b2++) pqx[b2] = tid ^ (1 << (5 + b2));

        // phi_0 = e_init ; phi_1 = H' e_init (analytic single column)
        float curs[8];
        u64 cur2[4], prevn2[4], psr2[4], psi2[4];
        const float cr0 = s_cr[0], ci1 = s_ci[1];
#pragma unroll
        for (int e = 0; e < 4; e++) {
            float p0v[2], p1v[2];
#pragma unroll
            for (int c = 0; c < 2; c++) {
                const int s = (e << 10) | (tid << 1) | c;
                p0v[c] = (s == init) ? 1.f : 0.f;
                float p1 = (s == init) ? diag[e * 2 + c] : 0.f;
                const int d = s ^ init;
#pragma unroll
                for (int i = 0; i < NQ; i++)
                    if (d == (1 << i)) p1 = px[i];
                p1v[c] = p1;
            }
            curs[2 * e]     = p1v[0];
            curs[2 * e + 1] = p1v[1];
            cur2[e]   = pk2(p1v[0], p1v[1]);
            prevn2[e] = pk2(-p0v[0], -p0v[1]);
            psr2[e]   = pk2(cr0 * p0v[0], cr0 * p0v[1]);
            psi2[e]   = pk2(ci1 * p1v[0], ci1 * p1v[1]);
            buf0[(e << 9) | tid] = cur2[e];
        }
        __syncthreads();

        for (int k = 2; k <= K; k += 2) {
            cheb_term<true>(cur2, curs, prevn2, psr2, psi2,
                            diag2, pxp, buf0, buf1, pqi, pqx, tid, s_cr[k]);
            if (k + 1 <= K)
                cheb_term<false>(cur2, curs, prevn2, psr2, psi2,
                                 diag2, pxp, buf1, buf0, pqi, pqx, tid, s_ci[k + 1]);
        }

        // publish state + release flag
#pragma unroll
        for (int e = 0; e < 4; e++) {
            float r0, r1, i0, i1;
            upk2(psr2[e], r0, r1);
            upk2(psi2[e], i0, i1);
            const int s = (e << 10) | (tid << 1);
            g_states[t][s]     = make_float2(r0, i0);
            g_states[t][s | 1] = make_float2(r1, i1);
        }
        __syncthreads();
        if (tid == 0) {
            __threadfence();
            st_release(&g_flag[t], 1);
        }
        __syncthreads();   // pool reuse guard before measure phase
    } else {
        // ================= WAIT on evolve(t) =================
        if (tid == 0) {
            while (ld_acquire(&g_flag[t]) == 0) __nanosleep(128);
            const int n = atomicAdd(&g_cnt[t], 1);
            if (n == 30) {               // last of 31 waiters: self-clean
                g_cnt[t]  = 0;
                g_flag[t] = 0;
            }
        }
        __syncthreads();
    }

    // ================= MEASURE (t, b) =================
    {
        float* re = pool;
        float* im = pool + DIM;
        int* p_raw = s_misc;
        int* nzm   = s_misc + NQ;
        int* nzp   = s_misc + 2 * NQ;
        int* s_nnz = s_misc + 3 * NQ;

        if (tid < NQ) p_raw[tid] = d_pauli[b * NQ + tid];

#pragma unroll
        for (int r = 0; r < DIM / 512; r++) {
            const int s = tid + (r << 9);
            const float2 v = __ldcg(&g_states[t][s]);
            re[s] = v.x;
            im[s] = v.y;
        }
        __syncthreads();

        if (tid == 0) {
            int c = 0;
            for (int m = NQ - 1; m >= 0; m--) {
                const int p = p_raw[NQ - 1 - m];
                if (p != 2) { nzm[c] = m; nzp[c] = p; c++; }
            }
            *s_nnz = c;
        }
        __syncthreads();

        const int nnz = *s_nnz;
        int i = 0;
        for (; i + 1 < nnz; i += 2) {
            const int mh = nzm[i], ml = nzm[i + 1];
            const int ph_ = nzp[i], pl = nzp[i + 1];
            const int lml = (1 << ml) - 1;
            const int lmh = (1 << mh) - 1;
#pragma unroll
            for (int r = 0; r < (DIM / 4) / 512; r++) {
                const int g  = tid + (r << 9);
                const int x  = ((g & ~lml) << 1) | (g & lml);
                const int s00 = ((x & ~lmh) << 1) | (x & lmh);
                const int s01 = s00 | (1 << ml);
                const int s10 = s00 | (1 << mh);
                const int s11 = s10 | (1 << ml);
                const float r00 = re[s00], i00 = im[s00];
                const float r01 = re[s01], i01 = im[s01];
                const float r10 = re[s10], i10 = im[s10];
                const float r11 = re[s11], i11 = im[s11];
                float a0r, a0i, a1r, a1i, b0r, b0i, b1r, b1i;
                if (pl == 0) {
                    a0r = r00 + r01; a0i = i00 + i01; a1r = r00 - r01; a1i = i00 - i01;
                    b0r = r10 + r11; b0i = i10 + i11; b1r = r10 - r11; b1i = i10 - i11;
                } else {
                    a0r = r00 + i01; a0i = i00 - r01; a1r = r00 - i01; a1i = i00 + r01;
                    b0r = r10 + i11; b0i = i10 - r11; b1r = r10 - i11; b1i = i10 + r11;
                }
                float o00r, o00i, o01r, o01i, o10r, o10i, o11r, o11i;
                if (ph_ == 0) {
                    o00r = a0r + b0r; o00i = a0i + b0i; o10r = a0r - b0r; o10i = a0i - b0i;
                    o01r = a1r + b1r; o01i = a1i + b1i; o11r = a1r - b1r; o11i = a1i - b1i;
                } else {
                    o00r = a0r + b0i; o00i = a0i - b0r; o10r = a0r - b0i; o10i = a0i + b0r;
                    o01r = a1r + b1i; o01i = a1i - b1r; o11r = a1r - b1i; o11i = a1i + b1r;
                }
                re[s00] = o00r * 0.5f; im[s00] = o00i * 0.5f;
                re[s01] = o01r * 0.5f; im[s01] = o01i * 0.5f;
                re[s10] = o10r * 0.5f; im[s10] = o10i * 0.5f;
                re[s11] = o11r * 0.5f; im[s11] = o11i * 0.5f;
            }
            __syncthreads();
        }
        if (i < nnz) {
            const int m = nzm[i], p = nzp[i];
            const int lm = (1 << m) - 1;
            const float s2 = 0.70710678118654752f;
#pragma unroll
            for (int r = 0; r < (DIM / 2) / 512; r++) {
                const int q  = tid + (r << 9);
                const int s0 = ((q & ~lm) << 1) | (q & lm);
                const int s1 = s0 | (1 << m);
                const float r0 = re[s0], i0 = im[s0];
                const float r1 = re[s1], i1 = im[s1];
                float nr0, ni0, nr1, ni1;
                if (p == 0) { nr0 = r0 + r1; ni0 = i0 + i1; nr1 = r0 - r1; ni1 = i0 - i1; }
                else        { nr0 = r0 + i1; ni0 = i0 - r1; nr1 = r0 - i1; ni1 = i0 + r1; }
                re[s0] = nr0 * s2; im[s0] = ni0 * s2;
                re[s1] = nr1 * s2; im[s1] = ni1 * s2;
            }
            __syncthreads();
        }

        if (tid < SHOTS) {
            const int base2 = (t * BB + b) * SHOTS;
            const int idx   = d_idx[base2 + tid];
            const float pr  = re[idx];
            const float pi  = im[idx];
            d_out[base2 + tid] = pr * pr + pi * pi;
        }
    }
}

// ---------------------------------------------------------------------------
extern "C" void kernel_launch(void* const* d_in, const int* in_sizes, int n_in,
                              void* d_out, int out_size)
{
    const int*   d_init  = (const int*)  d_in[0];
    const float* d_ts    = (const float*)d_in[1];
    const int*   d_pauli = (const int*)  d_in[2];
    const int*   d_idx   = (const int*)  d_in[3];
    const float* d_px    = (const float*)d_in[4];
    const float* d_pzz   = (const float*)d_in[5];

    fused_kernel<<<TT * BB, 512>>>(d_init, d_ts, d_pauli, d_idx,
                                   d_px, d_pzz, (float*)d_out);
}

// round 9
// speedup vs baseline: 1.2208x; 1.1112x over previous
#include <cuda_runtime.h>
#include <math.h>
#include <stdint.h>

#define NQ    12
#define DIM   4096
#define TT    8
#define BB    32
#define SHOTS 256
#define KMAX  80
#define HPAIR 1024          // u64 pairs per CTA half (2048 floats)

typedef unsigned long long u64;

// Evolved states exp(-i t H)|init>, one complex vector per t, plus sync flags.
__device__ float2 g_states[TT][DIM];
__device__ int    g_flag[TT];   // counts ranks published (0..2); self-cleaning
__device__ int    g_cnt[TT];    // consumer count for self-clean

__device__ __forceinline__ int ld_acquire(const int* p) {
    int v;
    asm volatile("ld.acquire.gpu.s32 %0, [%1];" : "=r"(v) : "l"(p) : "memory");
    return v;
}
__device__ __forceinline__ uint32_t smem_u32(const void* p) {
    uint32_t a;
    asm("{ .reg .u64 t; cvta.to.shared.u64 t, %1; cvt.u32.u64 %0, t; }"
        : "=r"(a) : "l"(p));
    return a;
}
__device__ __forceinline__ uint32_t mapa32(uint32_t a, uint32_t r) {
    uint32_t d;
    asm("mapa.shared::cluster.u32 %0, %1, %2;" : "=r"(d) : "r"(a), "r"(r));
    return d;
}
__device__ __forceinline__ void mbar_wait(uint32_t bar, uint32_t parity) {
    asm volatile(
        "{\n\t.reg .pred P;\n\t"
        "WL_%=:\n\t"
        "mbarrier.try_wait.parity.acquire.cta.shared::cta.b64 P, [%0], %1, 0x989680;\n\t"
        "@P bra.uni WD_%=;\n\t"
        "bra.uni WL_%=;\n\t"
        "WD_%=:\n\t}"
        :: "r"(bar), "r"(parity) : "memory");
}
__device__ __forceinline__ void mbar_expect(uint32_t bar, uint32_t bytes) {
    asm volatile("mbarrier.arrive.expect_tx.shared.b64 _, [%0], %1;"
                 :: "r"(bar), "r"(bytes) : "memory");
}
__device__ __forceinline__ void bulk_s2s(uint32_t dst, uint32_t src,
                                         uint32_t bytes, uint32_t rbar) {
    asm volatile(
        "cp.async.bulk.shared::cluster.shared::cta.mbarrier::complete_tx::bytes "
        "[%0], [%1], %2, [%3];"
        :: "r"(dst), "r"(src), "r"(bytes), "r"(rbar) : "memory");
}

// ---- packed f32x2 helpers ----
__device__ __forceinline__ u64 pk2(float lo, float hi) {
    u64 r; asm("mov.b64 %0, {%1,%2};" : "=l"(r) : "f"(lo), "f"(hi)); return r;
}
__device__ __forceinline__ void upk2(u64 v, float& lo, float& hi) {
    asm("mov.b64 {%0,%1}, %2;" : "=f"(lo), "=f"(hi) : "l"(v));
}
__device__ __forceinline__ u64 fma2_(u64 a, u64 b, u64 c) {
    u64 d; asm("fma.rn.f32x2 %0, %1, %2, %3;" : "=l"(d) : "l"(a), "l"(b), "l"(c));
    return d;
}
__device__ __forceinline__ u64 mul2_(u64 a, u64 b) {
    u64 d; asm("mul.rn.f32x2 %0, %1, %2;" : "=l"(d) : "l"(a), "l"(b)); return d;
}

// ---------------------------------------------------------------------------
// One Chebyshev term on a CTA half (2048 entries, 4 per thread).
// Local s = (e<<10)|(tid<<1)|c, e,c in {0,1}; global s adds rank<<11.
// Taps: bit0 = pair swap (regs), bit10 = e (regs), bits1..9 local smem,
// bit11 = peer mirror (read LAST, after tx-barrier wait, so the 8KB DSMEM
// bulk transfer hides under the own-tap crossbar phase).
// ---------------------------------------------------------------------------
template<bool EVEN>
__device__ __forceinline__ void cheb_term(
    u64 (&cur2)[2], float (&curs)[4], u64 (&prevn2)[2],
    u64 (&psr2)[2], u64 (&psi2)[2],
    const u64 (&diag2)[2], const u64 (&pxp)[12],
    const u64* __restrict__ SRC, u64* __restrict__ DST,
    const u64* __restrict__ MIR,
    uint32_t bar_in, int& ph_in, bool do_wait,
    uint32_t bulk_dst, uint32_t bulk_src, uint32_t bulk_rbar, bool do_send,
    const int (&pq)[9], int tid, float coef)
{
    u64 a2[2];
    a2[0] = mul2_(diag2[0], cur2[0]);
    a2[1] = mul2_(diag2[1], cur2[1]);
    a2[0] = fma2_(pxp[0], pk2(curs[1], curs[0]), a2[0]);
    a2[1] = fma2_(pxp[0], pk2(curs[3], curs[2]), a2[1]);
    a2[0] = fma2_(pxp[10], cur2[1], a2[0]);
    a2[1] = fma2_(pxp[10], cur2[0], a2[1]);
    // own-half smem taps, bits 1..9 (18 conflict-free LDS.64)
#pragma unroll
    for (int bi = 0; bi < 9; bi++) {
        const u64* p = SRC + pq[bi];
        a2[0] = fma2_(pxp[1 + bi], p[0],   a2[0]);
        a2[1] = fma2_(pxp[1 + bi], p[512], a2[1]);
    }
    // wait for peer mirror (usually already complete), then post next expect
    if (do_wait) {
        mbar_wait(bar_in, (uint32_t)ph_in);
        ph_in ^= 1;
        if (tid == 0) mbar_expect(bar_in, 8192u);
    }
    // peer tap, bit 11
    a2[0] = fma2_(pxp[11], MIR[tid],       a2[0]);
    a2[1] = fma2_(pxp[11], MIR[tid + 512], a2[1]);

    const u64 TWO2 = pk2(2.f, 2.f);
    const u64 M12  = pk2(-1.f, -1.f);
    const u64 C2   = pk2(coef, coef);
#pragma unroll
    for (int e = 0; e < 2; e++) {
        const u64 nx = fma2_(TWO2, a2[e], prevn2[e]);   // 2*acc - prev
        DST[(e << 9) | tid] = nx;
        prevn2[e] = mul2_(cur2[e], M12);
        cur2[e]   = nx;
        if (EVEN) psr2[e] = fma2_(C2, nx, psr2[e]);
        else      psi2[e] = fma2_(C2, nx, psi2[e]);
    }
    upk2(cur2[0], curs[0], curs[1]);
    upk2(cur2[1], curs[2], curs[3]);

    __syncthreads();   // all DST stores visible (also covers next term's reads)

    if (do_send && tid == 0) {
        asm volatile("fence.proxy.async.shared::cta;" ::: "memory");
        bulk_s2s(bulk_dst, bulk_src, 8192u, bulk_rbar);
    }
}

// ---------------------------------------------------------------------------
// Fused persistent kernel. 256 CTAs x 512 threads, cluster size 2.
//   bid 0..15 : evolve t=bid>>1, rank=bid&1 (2-CTA cluster per t);
//               afterwards measure (t, b=rank).
//   bid >= 16 : wait on flag[t]==2, then measure (t, b=2+...)
// ---------------------------------------------------------------------------
__global__ void __cluster_dims__(2, 1, 1) __launch_bounds__(512, 1)
fused_kernel(const int* __restrict__ d_init,
             const float* __restrict__ d_ts,
             const int* __restrict__ d_pauli,
             const int* __restrict__ d_idx,
             const float* __restrict__ d_px,
             const float* __restrict__ d_pzz,
             float* __restrict__ d_out)
{
    // pool (32KB): evolve buf0|buf1|mir0|mir1 (8KB each u64[1024]); coeffs after.
    // measure reuses [0, DIM) = re, [DIM, 2*DIM) = im.
    __shared__ __align__(16) float pool[2 * DIM + 2 * (KMAX + 1)];
    __shared__ __align__(8) unsigned long long s_bar[2];
    __shared__ int s_misc[3 * NQ + 2];

    const int tid = threadIdx.x;
    const int bid = blockIdx.x;

    int t, b;
    if (bid < 2 * TT) { t = bid >> 1; b = bid & 1; }
    else { const int j = bid - 2 * TT; t = j / 30; b = 2 + j % 30; }

    if (bid < 2 * TT) {
        // ================= EVOLVE (t, rank) =================
        u64* bufs = reinterpret_cast<u64*>(pool);
        u64* buf0 = bufs;                 // phi even-gen
        u64* buf1 = bufs + HPAIR;         // phi odd-gen
        u64* mir0 = bufs + 2 * HPAIR;     // peer phi even-gen
        u64* mir1 = bufs + 3 * HPAIR;     // peer phi odd-gen
        float* s_cr = pool + 2 * DIM;
        float* s_ci = s_cr + (KMAX + 1);

        uint32_t rank;
        asm("mov.u32 %0, %%cluster_ctarank;" : "=r"(rank));
        const uint32_t peer = rank ^ 1u;

        float px[NQ];
        float lambda = 0.f;
#pragma unroll
        for (int i = 0; i < NQ; i++) { px[i] = d_px[i]; lambda += fabsf(px[i]); }
        float pzz[NQ - 1];
#pragma unroll
        for (int i = 0; i < NQ - 1; i++) { pzz[i] = d_pzz[i]; lambda += fabsf(pzz[i]); }
        if (lambda < 1e-20f) lambda = 1e-20f;
        const float inv_l = 1.0f / lambda;
#pragma unroll
        for (int i = 0; i < NQ; i++) px[i] *= inv_l;

        u64 pxp[12];
#pragma unroll
        for (int i = 0; i < NQ; i++) pxp[i] = pk2(px[i], px[i]);

        // scaled diagonal for owned entries: s = (rank<<11)|(e<<10)|(tid<<1)|c
        float diag[4];
#pragma unroll
        for (int e = 0; e < 2; e++) {
#pragma unroll
            for (int c = 0; c < 2; c++) {
                const int s = ((int)rank << 11) | (e << 10) | (tid << 1) | c;
                float d = 0.f;
#pragma unroll
                for (int i = 0; i < NQ - 1; i++) {
                    const int bi = (s >> i) & 1;
                    const int bj = (s >> (i + 1)) & 1;
                    d += (bi == bj) ? pzz[i] : -pzz[i];
                }
                diag[e * 2 + c] = d * inv_l;
            }
        }
        u64 diag2[2] = { pk2(diag[0], diag[1]), pk2(diag[2], diag[3]) };

        // thread 0: Bessel coefficients + adaptive trim + barrier init
        if (tid == 0) {
            double x = (double)d_ts[t] * (double)lambda;
            if (x < 1e-5) x = 1e-5;
            int K = (int)ceil(x) + 16;
            if (K > KMAX) K = KMAX;
            if (K < 2)    K = 2;
            const int M = K + 14;
            double v[KMAX + 16];
            v[M] = 1e-30;
            const double inv_x = 1.0 / x;
            double up = 0.0;
            for (int k = M; k >= 1; k--) {
                const double nv = (2.0 * (double)k * inv_x) * v[k] - up;
                up = v[k];
                v[k - 1] = nv;
            }
            double S = v[0];
            for (int m = 2; m <= M; m += 2) S += 2.0 * v[m];
            const double invS = 1.0 / S;
            while (K > 2 && fabs(v[K] * invS) < 2e-4) K--;   // adaptive trim
            for (int k = 0; k <= K; k++) {
                const double Jk = v[k] * invS;
                const double c  = (k == 0) ? Jk : 2.0 * Jk;
                float cr = 0.f, ci = 0.f;
                switch (k & 3) {         // (-i)^k
                    case 0: cr = (float)c;  break;
                    case 1: ci = (float)-c; break;
                    case 2: cr = (float)-c; break;
                    case 3: ci = (float)c;  break;
                }
                s_cr[k] = cr;
                s_ci[k] = ci;
            }
            s_misc[0] = K;
            // init tx barriers (1 arrival per phase = the arrive.expect_tx)
            const uint32_t b0 = smem_u32(&s_bar[0]);
            const uint32_t b1 = smem_u32(&s_bar[1]);
            asm volatile("mbarrier.init.shared.b64 [%0], 1;" :: "r"(b0) : "memory");
            asm volatile("mbarrier.init.shared.b64 [%0], 1;" :: "r"(b1) : "memory");
            mbar_expect(b0, 8192u);      // phase 0 of stage 0 (gen 2)
            mbar_expect(b1, 8192u);      // phase 0 of stage 1 (gen 3)
        }
        __syncthreads();
        asm volatile("barrier.cluster.arrive.aligned;" ::: "memory");
        asm volatile("barrier.cluster.wait.aligned;"   ::: "memory");

        const int K    = s_misc[0];
        const int init = *d_init;

        int pq[9];
#pragma unroll
        for (int b2 = 0; b2 < 9; b2++) pq[b2] = tid ^ (1 << b2);

        // addresses
        const uint32_t bar0 = smem_u32(&s_bar[0]);
        const uint32_t bar1 = smem_u32(&s_bar[1]);
        const uint32_t mir0a = smem_u32(mir0);
        const uint32_t mir1a = smem_u32(mir1);
        const uint32_t buf0a = smem_u32(buf0);
        const uint32_t buf1a = smem_u32(buf1);
        const uint32_t pmir0 = mapa32(mir0a, peer);
        const uint32_t pmir1 = mapa32(mir1a, peer);
        const uint32_t pbar0 = mapa32(bar0, peer);
        const uint32_t pbar1 = mapa32(bar1, peer);

        // phi_0 = e_init ; phi_1 = H' e_init (analytic), own half + peer mirror
        float curs[4];
        u64 cur2[2], prevn2[2], psr2[2], psi2[2];
        const float cr0 = s_cr[0], ci1 = s_ci[1];
#pragma unroll
        for (int e = 0; e < 2; e++) {
            float p0v[2], p1v[2], q1v[2];
#pragma unroll
            for (int c = 0; c < 2; c++) {
                const int so = ((int)rank << 11) | (e << 10) | (tid << 1) | c;
                const int sp = ((int)peer << 11) | (e << 10) | (tid << 1) | c;
                p0v[c] = (so == init) ? 1.f : 0.f;
                float p1 = (so == init) ? diag[e * 2 + c] : 0.f;
                int d = so ^ init;
#pragma unroll
                for (int i = 0; i < NQ; i++)
                    if (d == (1 << i)) p1 = px[i];
                p1v[c] = p1;
                // peer's phi_1 entry (diag of sp needed only when sp == init)
                float q1 = 0.f;
                if (sp == init) {
                    float dd = 0.f;
#pragma unroll
                    for (int i = 0; i < NQ - 1; i++) {
                        const int bi = (sp >> i) & 1;
                        const int bj = (sp >> (i + 1)) & 1;
                        dd += (bi == bj) ? pzz[i] : -pzz[i];
                    }
                    q1 = dd * inv_l;
                }
                d = sp ^ init;
#pragma unroll
                for (int i = 0; i < NQ; i++)
                    if (d == (1 << i)) q1 = px[i];
                q1v[c] = q1;
            }
            curs[2 * e]     = p1v[0];
            curs[2 * e + 1] = p1v[1];
            cur2[e]   = pk2(p1v[0], p1v[1]);
            prevn2[e] = pk2(-p0v[0], -p0v[1]);
            psr2[e]   = pk2(cr0 * p0v[0], cr0 * p0v[1]);
            psi2[e]   = pk2(ci1 * p1v[0], ci1 * p1v[1]);
            buf1[(e << 9) | tid] = cur2[e];          // phi_1 lives in buf1
            mir1[(e << 9) | tid] = pk2(q1v[0], q1v[1]); // peer phi_1 (analytic)
        }
        __syncthreads();

        int ph0 = 0, ph1 = 0;
        for (int k = 2; k <= K; k += 2) {
            // even k: consumes gen k-1 (stage 1: buf1/mir1), produces stage 0
            cheb_term<true>(cur2, curs, prevn2, psr2, psi2, diag2, pxp,
                            buf1, buf0, mir1,
                            bar1, ph1, (k > 2),
                            pmir0, buf0a, pbar0, (k < K),
                            pq, tid, s_cr[k]);
            if (k + 1 <= K)
                cheb_term<false>(cur2, curs, prevn2, psr2, psi2, diag2, pxp,
                                 buf0, buf1, mir0,
                                 bar0, ph0, true,
                                 pmir1, buf1a, pbar1, (k + 1 < K),
                                 pq, tid, s_ci[k + 1]);
        }

        // publish my half + count flag
#pragma unroll
        for (int e = 0; e < 2; e++) {
            float r0, r1, i0, i1;
            upk2(psr2[e], r0, r1);
            upk2(psi2[e], i0, i1);
            const int s = ((int)rank << 11) | (e << 10) | (tid << 1);
            g_states[t][s]     = make_float2(r0, i0);
            g_states[t][s | 1] = make_float2(r1, i1);
        }
        __syncthreads();
        if (tid == 0) {
            __threadfence();
            atomicAdd(&g_flag[t], 1);
        }
        // keep cluster alive until both ranks are done touching peer smem
        asm volatile("barrier.cluster.arrive.aligned;" ::: "memory");
        asm volatile("barrier.cluster.wait.aligned;"   ::: "memory");
    }

    // ================= WAIT for both halves of t =================
    if (tid == 0) {
        while (ld_acquire(&g_flag[t]) < 2) __nanosleep(64);
        const int n = atomicAdd(&g_cnt[t], 1);
        if (n == 31) {               // last of 32 consumers: self-clean
            g_cnt[t]  = 0;
            g_flag[t] = 0;
        }
    }
    __syncthreads();

    // ================= MEASURE (t, b) =================
    {
        float* re = pool;
        float* im = pool + DIM;
        int* p_raw = s_misc;
        int* nzm   = s_misc + NQ;
        int* nzp   = s_misc + 2 * NQ;
        int* s_nnz = s_misc + 3 * NQ;

        if (tid < NQ) p_raw[tid] = d_pauli[b * NQ + tid];

#pragma unroll
        for (int r = 0; r < DIM / 512; r++) {
            const int s = tid + (r << 9);
            const float2 v = __ldcg(&g_states[t][s]);
            re[s] = v.x;
            im[s] = v.y;
        }
        __syncthreads();

        if (tid == 0) {
            int c = 0;
            for (int m = NQ - 1; m >= 0; m--) {
                const int p = p_raw[NQ - 1 - m];
                if (p != 2) { nzm[c] = m; nzp[c] = p; c++; }
            }
            *s_nnz = c;
        }
        __syncthreads();

        const int nnz = *s_nnz;
        int i = 0;
        for (; i + 1 < nnz; i += 2) {
            const int mh = nzm[i], ml = nzm[i + 1];
            const int ph_ = nzp[i], pl = nzp[i + 1];
            const int lml = (1 << ml) - 1;
            const int lmh = (1 << mh) - 1;
#pragma unroll
            for (int r = 0; r < (DIM / 4) / 512; r++) {
                const int g  = tid + (r << 9);
                const int x  = ((g & ~lml) << 1) | (g & lml);
                const int s00 = ((x & ~lmh) << 1) | (x & lmh);
                const int s01 = s00 | (1 << ml);
                const int s10 = s00 | (1 << mh);
                const int s11 = s10 | (1 << ml);
                const float r00 = re[s00], i00 = im[s00];
                const float r01 = re[s01], i01 = im[s01];
                const float r10 = re[s10], i10 = im[s10];
                const float r11 = re[s11], i11 = im[s11];
                float a0r, a0i, a1r, a1i, b0r, b0i, b1r, b1i;
                if (pl == 0) {
                    a0r = r00 + r01; a0i = i00 + i01; a1r = r00 - r01; a1i = i00 - i01;
                    b0r = r10 + r11; b0i = i10 + i11; b1r = r10 - r11; b1i = i10 - i11;
                } else {
                    a0r = r00 + i01; a0i = i00 - r01; a1r = r00 - i01; a1i = i00 + r01;
                    b0r = r10 + i11; b0i = i10 - r11; b1r = r10 - i11; b1i = i10 + r11;
                }
                float o00r, o00i, o01r, o01i, o10r, o10i, o11r, o11i;
                if (ph_ == 0) {
                    o00r = a0r + b0r; o00i = a0i + b0i; o10r = a0r - b0r; o10i = a0i - b0i;
                    o01r = a1r + b1r; o01i = a1i + b1i; o11r = a1r - b1r; o11i = a1i - b1i;
                } else {
                    o00r = a0r + b0i; o00i = a0i - b0r; o10r = a0r - b0i; o10i = a0i + b0r;
                    o01r = a1r + b1i; o01i = a1i - b1r; o11r = a1r - b1i; o11i = a1i + b1r;
                }
                re[s00] = o00r * 0.5f; im[s00] = o00i * 0.5f;
                re[s01] = o01r * 0.5f; im[s01] = o01i * 0.5f;
                re[s10] = o10r * 0.5f; im[s10] = o10i * 0.5f;
                re[s11] = o11r * 0.5f; im[s11] = o11i * 0.5f;
            }
            __syncthreads();
        }
        if (i < nnz) {
            const int m = nzm[i], p = nzp[i];
            const int lm = (1 << m) - 1;
            const float s2 = 0.70710678118654752f;
#pragma unroll
            for (int r = 0; r < (DIM / 2) / 512; r++) {
                const int q  = tid + (r << 9);
                const int s0 = ((q & ~lm) << 1) | (q & lm);
                const int s1 = s0 | (1 << m);
                const float r0 = re[s0], i0 = im[s0];
                const float r1 = re[s1], i1 = im[s1];
                float nr0, ni0, nr1, ni1;
                if (p == 0) { nr0 = r0 + r1; ni0 = i0 + i1; nr1 = r0 - r1; ni1 = i0 - i1; }
                else        { nr0 = r0 + i1; ni0 = i0 - r1; nr1 = r0 - i1; ni1 = i0 + r1; }
                re[s0] = nr0 * s2; im[s0] = ni0 * s2;
                re[s1] = nr1 * s2; im[s1] = ni1 * s2;
            }
            __syncthreads();
        }

        if (tid < SHOTS) {
            const int base2 = (t * BB + b) * SHOTS;
            const int idx   = d_idx[base2 + tid];
            const float pr  = re[idx];
            const float pi  = im[idx];
            d_out[base2 + tid] = pr * pr + pi * pi;
        }
    }
}

// ---------------------------------------------------------------------------
extern "C" void kernel_launch(void* const* d_in, const int* in_sizes, int n_in,
                              void* d_out, int out_size)
{
    const int*   d_init  = (const int*)  d_in[0];
    const float* d_ts    = (const float*)d_in[1];
    const int*   d_pauli = (const int*)  d_in[2];
    const int*   d_idx   = (const int*)  d_in[3];
    const float* d_px    = (const float*)d_in[4];
    const float* d_pzz   = (const float*)d_in[5];

    fused_kernel<<<TT * BB, 512>>>(d_init, d_ts, d_pauli, d_idx,
                                   d_px, d_pzz, (float*)d_out);
}